// round 1
// baseline (speedup 1.0000x reference)
#include <cuda_runtime.h>
#include <math.h>

#define B_ 32
#define S_ 64
#define T_ 16
#define U_ 1024
#define E_ 256
#define V_ 20200
#define G_ 3072   /* 3*U */

// ---------------- device scratch (static globals; no runtime alloc) ----------------
__device__ float d_xemb[(S_*B_)*E_];        // [s*32+b][256]
__device__ float d_gxall[S_*B_*G_];         // [s][b][3072]  (x@Wx + b_in, all steps)
__device__ float d_hbuf[2][B_*U_];          // ping-pong hidden
__device__ float d_enc[B_*S_*U_];           // encoded [b][s][u]
__device__ float d_pre[B_*S_*U_];           // W1(encoded)+b1 [b][s][u]
__device__ float d_gpart[5][B_*G_];         // split-K partials for h@Wh / x@dec_Wx
__device__ float d_qpart[8][B_*U_];         // split-K partials for dec_h@W2
__device__ float d_xcat[B_*(U_+E_)];        // [ctx, Ed[tok]] per step
__device__ float d_Hall[T_*B_*U_];          // decoder hidden states, rows t*32+b
__device__ float d_logits_alt[T_*B_*V_];    // logits scratch (preds-only output case)

// ---------------- embedding gather ----------------
__global__ void embed_src(const int* __restrict__ enc_in, const float* __restrict__ Ee) {
    int idx = blockIdx.x * 256 + threadIdx.x;     // 2048*256 total
    int r = idx >> 8, e = idx & 255;
    int s = r >> 5, b = r & 31;
    d_xemb[r * E_ + e] = Ee[(size_t)enc_in[b * S_ + s] * E_ + e];
}

// ---------------- generic fp32 tiled GEMM ----------------
// MODE 0: C[M,N] = A@B + bias (N multiple of BN)
// MODE 1: logits epilogue: row gm=(t*32+b) -> out row (b*16+t); N bounds-checked; +bias
// MODE 2: split-K partial: blockIdx.z covers K chunk [z*Kc, (z+1)*Kc), writes C + z*M*N, no bias
template<int BM, int BN, int BK, int TM, int TN, int MODE>
__global__ void gemm_k(const float* __restrict__ A, const float* __restrict__ B,
                       const float* __restrict__ bias, float* __restrict__ C,
                       int M, int N, int K, int Kc)
{
    static_assert(TM == 4 && TN == 4, "micro tile fixed at 4x4");
    constexpr int TX = BN / TN, TY = BM / TM, NT = TX * TY;
    __shared__ float As[BK][BM];
    __shared__ float Bs[BK][BN];

    const int tid = threadIdx.x;
    const int tx = tid % TX, ty = tid / TX;
    const int n0 = blockIdx.x * BN;
    const int m0 = blockIdx.y * BM;

    int k0 = 0, k1 = K;
    float* Cp = C;
    if (MODE == 2) { k0 = blockIdx.z * Kc; k1 = k0 + Kc; Cp = C + (size_t)blockIdx.z * M * N; }

    float acc[TM][TN];
#pragma unroll
    for (int i = 0; i < TM; i++)
#pragma unroll
        for (int j = 0; j < TN; j++) acc[i][j] = 0.f;

    for (int kt = k0; kt < k1; kt += BK) {
#pragma unroll
        for (int i = tid; i < BM * BK; i += NT) {
            int m = i / BK, k = i % BK;
            As[k][m] = A[(size_t)(m0 + m) * K + kt + k];
        }
#pragma unroll
        for (int i = tid; i < BK * BN; i += NT) {
            int k = i / BN, n = i % BN;
            int gn = n0 + n;
            float v = 0.f;
            if (MODE != 1 || gn < N) v = B[(size_t)(kt + k) * N + gn];
            Bs[k][n] = v;
        }
        __syncthreads();
#pragma unroll
        for (int kk = 0; kk < BK; kk++) {
            const float4 av = *reinterpret_cast<const float4*>(&As[kk][ty * TM]);
            const float4 bvv = *reinterpret_cast<const float4*>(&Bs[kk][tx * TN]);
            const float a[4] = {av.x, av.y, av.z, av.w};
            const float bb[4] = {bvv.x, bvv.y, bvv.z, bvv.w};
#pragma unroll
            for (int i = 0; i < TM; i++)
#pragma unroll
                for (int j = 0; j < TN; j++) acc[i][j] += a[i] * bb[j];
        }
        __syncthreads();
    }

#pragma unroll
    for (int i = 0; i < TM; i++) {
        const int gm = m0 + ty * TM + i;
#pragma unroll
        for (int j = 0; j < TN; j++) {
            const int gn = n0 + tx * TN + j;
            if (MODE == 0) {
                Cp[(size_t)gm * N + gn] = acc[i][j] + bias[gn];
            } else if (MODE == 1) {
                if (gn < N) {
                    int bb_ = gm & 31, tt_ = gm >> 5;           // gm = t*32+b
                    Cp[(size_t)(bb_ * T_ + tt_) * N + gn] = acc[i][j] + bias[gn];
                }
            } else {
                Cp[(size_t)gm * N + gn] = acc[i][j];
            }
        }
    }
}

// ---------------- GRU gate: encoder (reduce split-K partials of h@Wh) ----------------
__global__ void gru_gate_enc(const float* __restrict__ gx, const float* __restrict__ b_rec,
                             const float* __restrict__ h_in, float* __restrict__ h_out, int s)
{
    int idx = blockIdx.x * blockDim.x + threadIdx.x;   // 32768
    int b = idx >> 10, u = idx & 1023;
    const float* g = gx + (size_t)b * G_;
    float xz = g[u], xr = g[U_ + u], xc = g[2 * U_ + u];
    float hz = b_rec[u], hr = b_rec[U_ + u], hc = b_rec[2 * U_ + u];
#pragma unroll
    for (int ks = 0; ks < 4; ks++) {
        const float* gp = d_gpart[ks] + (size_t)b * G_;
        hz += gp[u]; hr += gp[U_ + u]; hc += gp[2 * U_ + u];
    }
    float z = 1.f / (1.f + expf(-(xz + hz)));
    float r = 1.f / (1.f + expf(-(xr + hr)));
    float c = tanhf(xc + r * hc);
    float h = z * h_in[idx] + (1.f - z) * c;
    h_out[idx] = h;
    d_enc[(size_t)b * (S_ * U_) + s * U_ + u] = h;
}

// ---------------- GRU gate: decoder (h0 = 0 -> gh = b_rec; h_new = (1-z)*c) ----------------
__global__ void gru_gate_dec(const float* __restrict__ b_in, const float* __restrict__ b_rec,
                             float* __restrict__ h_out, int t)
{
    int idx = blockIdx.x * blockDim.x + threadIdx.x;
    int b = idx >> 10, u = idx & 1023;
    float xz = b_in[u], xr = b_in[U_ + u], xc = b_in[2 * U_ + u];
#pragma unroll
    for (int ks = 0; ks < 5; ks++) {
        const float* gp = d_gpart[ks] + (size_t)b * G_;
        xz += gp[u]; xr += gp[U_ + u]; xc += gp[2 * U_ + u];
    }
    float hz = b_rec[u], hr = b_rec[U_ + u], hc = b_rec[2 * U_ + u];
    float z = 1.f / (1.f + expf(-(xz + hz)));
    float r = 1.f / (1.f + expf(-(xr + hr)));
    float c = tanhf(xc + r * hc);
    float h = (1.f - z) * c;
    h_out[idx] = h;
    d_Hall[(size_t)t * (B_ * U_) + idx] = h;
}

// ---------------- attention + context + embed concat (block per batch row) ----------------
__global__ void attn_ctx(const float* __restrict__ b2, const float* __restrict__ Va,
                         const float* __restrict__ bvp, const float* __restrict__ Ed,
                         const int* __restrict__ teacher, int t)
{
    const int b = blockIdx.x, tid = threadIdx.x;
    __shared__ float qs[U_];
    __shared__ float sc[S_];
    __shared__ float inv_s;

    for (int u = tid; u < U_; u += 256) {
        float v = b2[u];
#pragma unroll
        for (int ks = 0; ks < 8; ks++) v += d_qpart[ks][(size_t)b * U_ + u];
        qs[u] = v;
    }
    __syncthreads();

    const int w = tid >> 5, lane = tid & 31;
    for (int s = w; s < S_; s += 8) {
        const float* pr = d_pre + (size_t)b * (S_ * U_) + (size_t)s * U_;
        float p = 0.f;
        for (int u = lane; u < U_; u += 32) p += tanhf(pr[u] + qs[u]) * Va[u];
#pragma unroll
        for (int o = 16; o > 0; o >>= 1) p += __shfl_xor_sync(0xffffffffu, p, o);
        if (lane == 0) sc[s] = p + bvp[0];
    }
    __syncthreads();

    if (tid == 0) {
        float m = sc[0];
        for (int s = 1; s < S_; s++) m = fmaxf(m, sc[s]);
        float sum = 0.f;
        for (int s = 0; s < S_; s++) { float e = expf(sc[s] - m); sc[s] = e; sum += e; }
        inv_s = 1.f / sum;
    }
    __syncthreads();

    const float inv = inv_s;
    for (int u = tid; u < U_; u += 256) {
        float acc = 0.f;
        const float* eb = d_enc + (size_t)b * (S_ * U_) + u;
#pragma unroll 8
        for (int s = 0; s < S_; s++) acc += sc[s] * eb[(size_t)s * U_];
        d_xcat[(size_t)b * (U_ + E_) + u] = acc * inv;
    }
    const int tok = teacher[b * T_ + t];
    if (tid < E_) d_xcat[(size_t)b * (U_ + E_) + U_ + tid] = Ed[(size_t)tok * E_ + tid];
}

// ---------------- argmax (first-max tie rule, matches jnp.argmax) ----------------
__global__ void argmax_k(const float* __restrict__ logits, long long* outI, float* outF, int asFloat)
{
    const int row = blockIdx.x;          // row = b*16+t over logits [b][t][v]
    const float* p = logits + (size_t)row * V_;
    const int tid = threadIdx.x;
    float best = -INFINITY; int bi = 0;
    for (int v = tid; v < V_; v += 256) {
        float val = p[v];
        if (val > best) { best = val; bi = v; }
    }
    __shared__ float bvs[256]; __shared__ int bis[256];
    bvs[tid] = best; bis[tid] = bi;
    __syncthreads();
    for (int st = 128; st > 0; st >>= 1) {
        if (tid < st) {
            float ov = bvs[tid + st]; int oi = bis[tid + st];
            if (ov > bvs[tid] || (ov == bvs[tid] && oi < bis[tid])) { bvs[tid] = ov; bis[tid] = oi; }
        }
        __syncthreads();
    }
    if (tid == 0) {
        if (asFloat) outF[row] = (float)bis[0];
        else         outI[row] = (long long)bis[0];
    }
}

// ---------------- launcher ----------------
static float* symaddr(const void* sym) {
    void* p = nullptr;
    cudaGetSymbolAddress(&p, sym);
    return (float*)p;
}

extern "C" void kernel_launch(void* const* d_in, const int* in_sizes, int n_in,
                              void* d_out, int out_size)
{
    const int s0 = (n_in >= 22) ? 4 : 2;   // index of Ee (scalars may be omitted)
    const int*   enc_in  = (const int*)d_in[0];
    const int*   teacher = (const int*)d_in[1];
    const float* Ee      = (const float*)d_in[s0 + 0];
    const float* eWx     = (const float*)d_in[s0 + 1];
    const float* eWh     = (const float*)d_in[s0 + 2];
    const float* eb_in   = (const float*)d_in[s0 + 3];
    const float* eb_rec  = (const float*)d_in[s0 + 4];
    const float* Ed      = (const float*)d_in[s0 + 5];
    const float* dWx     = (const float*)d_in[s0 + 6];
    /* dec_Wh (s0+7) is multiplied by h0=0 -> unused */
    const float* db_in   = (const float*)d_in[s0 + 8];
    const float* db_rec  = (const float*)d_in[s0 + 9];
    const float* W1      = (const float*)d_in[s0 + 10];
    const float* b1      = (const float*)d_in[s0 + 11];
    const float* W2      = (const float*)d_in[s0 + 12];
    const float* b2      = (const float*)d_in[s0 + 13];
    const float* Va      = (const float*)d_in[s0 + 14];
    const float* bvp     = (const float*)d_in[s0 + 15];
    const float* Wf      = (const float*)d_in[s0 + 16];
    const float* bf      = (const float*)d_in[s0 + 17];

    float* xemb  = symaddr(d_xemb);
    float* gxall = symaddr(d_gxall);
    float* hbase = symaddr(d_hbuf);
    float* encp  = symaddr(d_enc);
    float* prep  = symaddr(d_pre);
    float* gpart = symaddr(d_gpart);
    float* qpart = symaddr(d_qpart);
    float* xcat  = symaddr(d_xcat);
    float* Hall  = symaddr(d_Hall);
    float* lalt  = symaddr(d_logits_alt);

    // output convention
    const long long LOGN = (long long)B_ * T_ * V_;   // 10,342,400
    float* logits_dst = (float*)d_out;
    long long* predI = nullptr; float* predF = nullptr; int asFloat = 0;
    if ((long long)out_size == LOGN + 512) { predF = (float*)d_out + LOGN; asFloat = 1; }
    else if ((long long)out_size == LOGN + 1024) { predI = (long long*)((float*)d_out + LOGN); }
    else if (out_size == 512) { logits_dst = lalt; predI = (long long*)d_out; }
    // else: logits only

    // h0 = 0
    cudaMemsetAsync(hbase, 0, (size_t)B_ * U_ * sizeof(float));

    // encoder: embed + gx for all steps at once
    embed_src<<<2048, 256>>>(enc_in, Ee);
    gemm_k<64,64,16,4,4,0><<<dim3(G_/64, (S_*B_)/64), 256>>>(xemb, eWx, eb_in, gxall,
                                                             S_*B_, G_, E_, 0);
    // encoder recurrence (64 serial steps): split-K h@Wh + gate
    for (int s = 0; s < S_; s++) {
        float* hin  = hbase + (size_t)(s & 1) * B_ * U_;
        float* hout = hbase + (size_t)((s + 1) & 1) * B_ * U_;
        gemm_k<32,64,16,4,4,2><<<dim3(G_/64, 1, 4), 128>>>(hin, eWh, nullptr, gpart,
                                                           B_, G_, U_, U_/4);
        gru_gate_enc<<<128, 256>>>(gxall + (size_t)s * B_ * G_, eb_rec, hin, hout, s);
    }

    // pre_enc = encoded @ W1 + b1
    gemm_k<64,64,16,4,4,0><<<dim3(U_/64, (B_*S_)/64), 256>>>(encp, W1, b1, prep,
                                                             B_*S_, U_, U_, 0);

    // decoder (16 serial steps); logits batched at the end
    for (int t = 0; t < T_; t++) {
        float* hin  = hbase + (size_t)(t & 1) * B_ * U_;
        float* hout = hbase + (size_t)((t + 1) & 1) * B_ * U_;
        gemm_k<32,64,16,4,4,2><<<dim3(U_/64, 1, 8), 128>>>(hin, W2, nullptr, qpart,
                                                           B_, U_, U_, U_/8);
        attn_ctx<<<B_, 256>>>(b2, Va, bvp, Ed, teacher, t);
        gemm_k<32,64,16,4,4,2><<<dim3(G_/64, 1, 5), 128>>>(xcat, dWx, nullptr, gpart,
                                                           B_, G_, U_+E_, (U_+E_)/5);
        gru_gate_dec<<<128, 256>>>(db_in, db_rec, hout, t);
    }

    // logits = Hall @ Wf + bf  (rows t*32+b scattered to out[b][t][:])
    gemm_k<64,64,16,4,4,1><<<dim3((V_+63)/64, (T_*B_)/64), 256>>>(Hall, Wf, bf, logits_dst,
                                                                  T_*B_, V_, U_, 0);

    if (predI || predF) argmax_k<<<T_*B_, 256>>>(logits_dst, predI, predF, asFloat);
}